// round 2
// baseline (speedup 1.0000x reference)
#include <cuda_runtime.h>
#include <math.h>
#include <stdint.h>

#define SEQN 2048
#define DIMN 2048
#define HEADS 16
#define DHEAD 128
#define NTILES 32          // SEQN / 64
#define SCALE_F 0.08838834764831845f  // 128^-0.5

// ---------------- device scratch (no cudaMalloc allowed) ----------------
__device__ float g_xn[SEQN * DIMN];          // rmsnorm output
__device__ float g_q [SEQN * DIMN];          // q projection [n, h*d]
__device__ float g_k [SEQN * DHEAD];
__device__ float g_v [SEQN * DHEAD];
__device__ float g_ao[SEQN * DIMN];          // attention output [n, h*d]
__device__ float g_sufv[(NTILES + 1) * DHEAD]; // suffix sums of v at 64-row tile boundaries

// ---------------- RMSNorm ----------------
__global__ void rmsnorm_kernel(const float* __restrict__ x,
                               const float* __restrict__ gamma)
{
    const int row = blockIdx.x;
    const int tid = threadIdx.x;
    const float* xr = x + (size_t)row * DIMN;

    float s = 0.f;
    for (int c = tid; c < DIMN; c += 256) { float v = xr[c]; s += v * v; }
    #pragma unroll
    for (int o = 16; o; o >>= 1) s += __shfl_xor_sync(0xffffffffu, s, o);

    __shared__ float red[8];
    __shared__ float inv_sh;
    if ((tid & 31) == 0) red[tid >> 5] = s;
    __syncthreads();
    if (tid == 0) {
        float t = 0.f;
        #pragma unroll
        for (int i = 0; i < 8; i++) t += red[i];
        inv_sh = rsqrtf(t / (float)DIMN + 1e-5f);
    }
    __syncthreads();
    const float inv = inv_sh;
    for (int c = tid; c < DIMN; c += 256)
        g_xn[(size_t)row * DIMN + c] = xr[c] * inv * gamma[c];
}

// ---------------- big fp32 GEMM: C[M,N] = A[M,K] @ B[K,N] ----------------
// 128x128 tile, BK=8, 256 threads, 8x8 per thread, float4 loads.
// Requires M,N multiples of 128 and K multiple of 8.
__global__ void sgemm128_kernel(const float* __restrict__ A,
                                const float* __restrict__ B,
                                float* __restrict__ C,
                                int M, int N, int K)
{
    __shared__ float As[8][128];   // [kk][m]
    __shared__ float Bs[8][128];   // [kk][n]

    const int tid = threadIdx.x;
    const int tx = tid & 15;       // col group 0..15
    const int ty = tid >> 4;       // row group 0..15
    const int m0 = blockIdx.y * 128, n0 = blockIdx.x * 128;

    // A tile load: 128 rows x 8 k, float4 along K
    const int a_row = tid >> 1;            // 0..127
    const int a_col = (tid & 1) * 4;       // 0 or 4
    // B tile load: 8 k-rows x 128 cols, float4 along N
    const int b_row = tid >> 5;            // 0..7
    const int b_col = (tid & 31) * 4;      // 0..124

    float acc[8][8];
    #pragma unroll
    for (int i = 0; i < 8; i++)
        #pragma unroll
        for (int j = 0; j < 8; j++) acc[i][j] = 0.f;

    for (int k0 = 0; k0 < K; k0 += 8) {
        float4 av = *(const float4*)(A + (size_t)(m0 + a_row) * K + k0 + a_col);
        float4 bv = *(const float4*)(B + (size_t)(k0 + b_row) * N + n0 + b_col);
        __syncthreads();
        As[a_col + 0][a_row] = av.x;
        As[a_col + 1][a_row] = av.y;
        As[a_col + 2][a_row] = av.z;
        As[a_col + 3][a_row] = av.w;
        *(float4*)&Bs[b_row][b_col] = bv;
        __syncthreads();
        #pragma unroll
        for (int kk = 0; kk < 8; kk++) {
            float a[8], b[8];
            #pragma unroll
            for (int i = 0; i < 8; i++) a[i] = As[kk][ty * 8 + i];
            #pragma unroll
            for (int j = 0; j < 8; j++) b[j] = Bs[kk][tx * 8 + j];
            #pragma unroll
            for (int i = 0; i < 8; i++)
                #pragma unroll
                for (int j = 0; j < 8; j++)
                    acc[i][j] = fmaf(a[i], b[j], acc[i][j]);
        }
    }

    #pragma unroll
    for (int i = 0; i < 8; i++) {
        float* crow = C + (size_t)(m0 + ty * 8 + i) * N + n0 + tx * 8;
        #pragma unroll
        for (int jv = 0; jv < 2; jv++) {
            float4 o;
            o.x = acc[i][jv * 4 + 0];
            o.y = acc[i][jv * 4 + 1];
            o.z = acc[i][jv * 4 + 2];
            o.w = acc[i][jv * 4 + 3];
            *(float4*)(crow + jv * 4) = o;
        }
    }
}

// ---------------- small fp32 GEMM (64x64 tile) for narrow-N projections ---------
__global__ void sgemm64_kernel(const float* __restrict__ A,
                               const float* __restrict__ B,
                               float* __restrict__ C,
                               int M, int N, int K)
{
    __shared__ float As[16 * 65];   // [kk][m], padded
    __shared__ float Bs[16 * 64];   // [kk][n]

    const int tid = threadIdx.x;
    const int tx = tid & 15, ty = tid >> 4;
    const int m0 = blockIdx.y * 64, n0 = blockIdx.x * 64;

    float c[4][4];
    #pragma unroll
    for (int i = 0; i < 4; i++)
        #pragma unroll
        for (int j = 0; j < 4; j++) c[i][j] = 0.f;

    for (int k0 = 0; k0 < K; k0 += 16) {
        for (int i = tid; i < 64 * 16; i += 256) {
            int m = i >> 4, kk = i & 15;
            As[kk * 65 + m] = A[(size_t)(m0 + m) * K + k0 + kk];
        }
        for (int i = tid; i < 16 * 64; i += 256) {
            int kk = i >> 6, n = i & 63;
            Bs[kk * 64 + n] = B[(size_t)(k0 + kk) * N + n0 + n];
        }
        __syncthreads();
        #pragma unroll
        for (int kk = 0; kk < 16; kk++) {
            float a[4], b[4];
            #pragma unroll
            for (int i = 0; i < 4; i++) a[i] = As[kk * 65 + ty * 4 + i];
            #pragma unroll
            for (int j = 0; j < 4; j++) b[j] = Bs[kk * 64 + tx * 4 + j];
            #pragma unroll
            for (int i = 0; i < 4; i++)
                #pragma unroll
                for (int j = 0; j < 4; j++)
                    c[i][j] = fmaf(a[i], b[j], c[i][j]);
        }
        __syncthreads();
    }
    #pragma unroll
    for (int i = 0; i < 4; i++)
        #pragma unroll
        for (int j = 0; j < 4; j++)
            C[(size_t)(m0 + ty * 4 + i) * N + n0 + tx * 4 + j] = c[i][j];
}

// ---------------- suffix sums of V at 64-row tile boundaries ----------------
// g_sufv[t][d] = sum_{j >= t*64} v[j][d], t in [0,32]
__global__ void suffix_kernel()
{
    const int d = threadIdx.x;   // 128 threads
    float run = 0.f;
    g_sufv[NTILES * DHEAD + d] = 0.f;
    for (int t = NTILES - 1; t >= 0; t--) {
        for (int i = (t + 1) * 64 - 1; i >= t * 64; i--)
            run += g_v[(size_t)i * DHEAD + d];
        g_sufv[t * DHEAD + d] = run;
    }
}

// ---------------- flash attention (fp32, online softmax, causal + 1e-10 mask) ------
// grid: (32 row-tiles, 16 heads), block 256 threads.
// smem (floats): Qs 64x129=8256, Ks(transposed)[128][68]=8704, Vs 64x132=8448,
//                Ss 64x65=4160, stats 4x64=256  -> 29824 floats = 119296 bytes
#define FLASH_SMEM_FLOATS (8256 + 8704 + 8448 + 4160 + 256)

__global__ void flash_kernel(const float* __restrict__ bias)
{
    extern __shared__ float sm[];
    float* Qs   = sm;
    float* Ks   = sm + 8256;
    float* Vs   = sm + 8256 + 8704;
    float* Ss   = sm + 8256 + 8704 + 8448;
    float* m_s  = Ss + 4160;
    float* l_s  = m_s + 64;
    float* fac_s = l_s + 64;
    float* e_s  = fac_s + 64;

    const int tid = threadIdx.x;
    const int tx = tid & 15, ty = tid >> 4;
    const int i0 = blockIdx.x * 64;
    const int h  = blockIdx.y;

    for (int idx = tid; idx < 64 * 128; idx += 256) {
        int r = idx >> 7, d = idx & 127;
        Qs[r * 129 + d] = g_q[(size_t)(i0 + r) * DIMN + h * DHEAD + d];
    }
    if (tid < 64) { m_s[tid] = -INFINITY; l_s[tid] = 0.f; }

    float acc[4][8];
    #pragma unroll
    for (int i = 0; i < 4; i++)
        #pragma unroll
        for (int d = 0; d < 8; d++) acc[i][d] = 0.f;
    __syncthreads();

    const int T = blockIdx.x + 1;   // causal: process tiles 0..T-1
    for (int jt = 0; jt < T; jt++) {
        const int j0 = jt * 64;
        for (int idx = tid; idx < 64 * 128; idx += 256) {
            int jr = idx >> 7, d = idx & 127;
            float kval = g_k[(size_t)(j0 + jr) * DHEAD + d];
            float vval = g_v[(size_t)(j0 + jr) * DHEAD + d];
            Ks[d * 68 + jr]  = kval;   // transposed: [d][j]
            Vs[jr * 132 + d] = vval;
        }
        __syncthreads();

        // scores: 4x4 per thread
        float s[4][4];
        #pragma unroll
        for (int i = 0; i < 4; i++)
            #pragma unroll
            for (int j = 0; j < 4; j++) s[i][j] = 0.f;
        #pragma unroll 4
        for (int kk = 0; kk < 128; kk++) {
            float a[4], b[4];
            #pragma unroll
            for (int i = 0; i < 4; i++) a[i] = Qs[(ty * 4 + i) * 129 + kk];
            #pragma unroll
            for (int j = 0; j < 4; j++) b[j] = Ks[kk * 68 + tx * 4 + j];
            #pragma unroll
            for (int i = 0; i < 4; i++)
                #pragma unroll
                for (int j = 0; j < 4; j++)
                    s[i][j] = fmaf(a[i], b[j], s[i][j]);
        }
        #pragma unroll
        for (int i = 0; i < 4; i++) {
            const int gi = i0 + ty * 4 + i;
            const float* brow = bias + ((size_t)h * SEQN + gi) * SEQN + j0;
            #pragma unroll
            for (int j = 0; j < 4; j++) {
                const int jj = tx * 4 + j;
                float val = s[i][j] * SCALE_F + brow[jj];
                if (j0 + jj > gi) val = 1e-10f;   // masked-but-participating
                Ss[(ty * 4 + i) * 65 + jj] = val;
            }
        }
        __syncthreads();

        // online-softmax row stats (threads 0..63, one row each)
        if (tid < 64) {
            const int r = tid;
            float mold = m_s[r];
            float mt = mold;
            for (int j = 0; j < 64; j++) mt = fmaxf(mt, Ss[r * 65 + j]);
            float fac = expf(mold - mt);  // expf(-inf)=0 on first tile
            float sum = 0.f;
            for (int j = 0; j < 64; j++) {
                float p = expf(Ss[r * 65 + j] - mt);
                Ss[r * 65 + j] = p;
                sum += p;
            }
            l_s[r] = l_s[r] * fac + sum;
            m_s[r] = mt;
            fac_s[r] = fac;
        }
        __syncthreads();

        // rescale + P@V
        #pragma unroll
        for (int i = 0; i < 4; i++) {
            const float f = fac_s[ty * 4 + i];
            #pragma unroll
            for (int d = 0; d < 8; d++) acc[i][d] *= f;
        }
        for (int jj = 0; jj < 64; jj++) {
            float p[4], vv[8];
            #pragma unroll
            for (int i = 0; i < 4; i++) p[i] = Ss[(ty * 4 + i) * 65 + jj];
            #pragma unroll
            for (int d = 0; d < 8; d++) vv[d] = Vs[jj * 132 + tx * 8 + d];
            #pragma unroll
            for (int i = 0; i < 4; i++)
                #pragma unroll
                for (int d = 0; d < 8; d++)
                    acc[i][d] = fmaf(p[i], vv[d], acc[i][d]);
        }
        __syncthreads();
    }

    // closed-form handling of the remaining fully-masked columns (value 1e-10)
    const int rem = SEQN - T * 64;
    if (rem > 0) {
        if (tid < 64) {
            const int r = tid;
            float mold = m_s[r];
            float mt = fmaxf(mold, 1e-10f);
            float fac = expf(mold - mt);
            float e   = expf(1e-10f - mt);
            l_s[r] = l_s[r] * fac + (float)rem * e;
            fac_s[r] = fac;
            e_s[r] = e;
        }
        __syncthreads();
        #pragma unroll
        for (int i = 0; i < 4; i++) {
            const float f = fac_s[ty * 4 + i];
            const float e = e_s[ty * 4 + i];
            #pragma unroll
            for (int d = 0; d < 8; d++)
                acc[i][d] = acc[i][d] * f + e * g_sufv[T * DHEAD + tx * 8 + d];
        }
    }
    __syncthreads();

    #pragma unroll
    for (int i = 0; i < 4; i++) {
        const float inv_l = 1.f / l_s[ty * 4 + i];
        const int gi = i0 + ty * 4 + i;
        #pragma unroll
        for (int d = 0; d < 8; d++)
            g_ao[(size_t)gi * DIMN + h * DHEAD + tx * 8 + d] = acc[i][d] * inv_l;
    }
}

// ---------------- launch ----------------
extern "C" void kernel_launch(void* const* d_in, const int* in_sizes, int n_in,
                              void* d_out, int out_size)
{
    const float* x        = (const float*)d_in[0];
    const float* pos_bias = (const float*)d_in[1];
    const float* gamma    = (const float*)d_in[2];
    const float* wq       = (const float*)d_in[3];
    const float* wk       = (const float*)d_in[4];
    const float* wv       = (const float*)d_in[5];
    const float* wo       = (const float*)d_in[6];
    float* out = (float*)d_out;

    float *xn_p, *q_p, *k_p, *v_p, *ao_p;
    cudaGetSymbolAddress((void**)&xn_p, g_xn);
    cudaGetSymbolAddress((void**)&q_p,  g_q);
    cudaGetSymbolAddress((void**)&k_p,  g_k);
    cudaGetSymbolAddress((void**)&v_p,  g_v);
    cudaGetSymbolAddress((void**)&ao_p, g_ao);

    cudaFuncSetAttribute(flash_kernel,
                         cudaFuncAttributeMaxDynamicSharedMemorySize,
                         FLASH_SMEM_FLOATS * (int)sizeof(float));

    rmsnorm_kernel<<<SEQN, 256>>>(x, gamma);

    sgemm128_kernel<<<dim3(DIMN / 128, SEQN / 128), 256>>>(xn_p, wq, q_p, SEQN, DIMN, DIMN);
    sgemm64_kernel<<<dim3(DHEAD / 64, SEQN / 64), 256>>>(xn_p, wk, k_p, SEQN, DHEAD, DIMN);
    sgemm64_kernel<<<dim3(DHEAD / 64, SEQN / 64), 256>>>(xn_p, wv, v_p, SEQN, DHEAD, DIMN);

    suffix_kernel<<<1, 128>>>();

    flash_kernel<<<dim3(NTILES, HEADS), 256, FLASH_SMEM_FLOATS * sizeof(float)>>>(pos_bias);

    sgemm128_kernel<<<dim3(DIMN / 128, SEQN / 128), 256>>>(ao_p, wo, out, SEQN, DIMN, DIMN);
}

// round 4
// speedup vs baseline: 1.5780x; 1.5780x over previous
#include <cuda_runtime.h>
#include <math.h>
#include <stdint.h>

#define SEQN 2048
#define DIMN 2048
#define HEADS 16
#define DHEAD 128
#define NTILES 32          // SEQN / 64
#define SCALE_F 0.08838834764831845f  // 128^-0.5

// ---------------- device scratch ----------------
__device__ float g_xn[SEQN * DIMN];
__device__ float g_q [SEQN * DIMN];
__device__ float g_k [SEQN * DHEAD];
__device__ float g_v [SEQN * DHEAD];
__device__ float g_ao[SEQN * DIMN];
__device__ float g_tsum[NTILES * DHEAD];
__device__ float g_sufv[(NTILES + 1) * DHEAD];

// ---------------- RMSNorm (float4) ----------------
__global__ void rmsnorm_kernel(const float* __restrict__ x,
                               const float* __restrict__ gamma)
{
    const int row = blockIdx.x;
    const int tid = threadIdx.x;
    const float4* xr4 = (const float4*)(x + (size_t)row * DIMN);
    const float4* g4  = (const float4*)gamma;
    float4* o4 = (float4*)(g_xn + (size_t)row * DIMN);

    float s = 0.f;
    float4 v0 = xr4[tid], v1 = xr4[tid + 256];
    s += v0.x*v0.x + v0.y*v0.y + v0.z*v0.z + v0.w*v0.w;
    s += v1.x*v1.x + v1.y*v1.y + v1.z*v1.z + v1.w*v1.w;
    #pragma unroll
    for (int o = 16; o; o >>= 1) s += __shfl_xor_sync(0xffffffffu, s, o);

    __shared__ float red[8];
    __shared__ float inv_sh;
    if ((tid & 31) == 0) red[tid >> 5] = s;
    __syncthreads();
    if (tid == 0) {
        float t = 0.f;
        #pragma unroll
        for (int i = 0; i < 8; i++) t += red[i];
        inv_sh = rsqrtf(t / (float)DIMN + 1e-5f);
    }
    __syncthreads();
    const float inv = inv_sh;
    float4 ga = g4[tid], gb = g4[tid + 256];
    float4 r0, r1;
    r0.x = v0.x*inv*ga.x; r0.y = v0.y*inv*ga.y; r0.z = v0.z*inv*ga.z; r0.w = v0.w*inv*ga.w;
    r1.x = v1.x*inv*gb.x; r1.y = v1.y*inv*gb.y; r1.z = v1.z*inv*gb.z; r1.w = v1.w*inv*gb.w;
    o4[tid] = r0; o4[tid + 256] = r1;
}

// ---------------- 128x128x16 double-buffered fp32 GEMM body ----------------
__device__ __forceinline__ void gemm128_body(
    const float* __restrict__ A, const float* __restrict__ B,
    float* __restrict__ C, int N, int K, int m0, int n0)
{
    __shared__ float As[2][16][128];
    __shared__ float Bs[2][16][128];

    const int tid = threadIdx.x;
    const int tx = tid & 15, ty = tid >> 4;
    const int a_row = tid >> 1;
    const int a_k   = (tid & 1) * 8;
    const int b_row = tid >> 5;            // 0..7
    const int b_col = (tid & 31) * 4;

    const float* Aptr  = A + (size_t)(m0 + a_row) * K + a_k;
    const float* Bptr0 = B + (size_t)b_row * N + n0 + b_col;
    const float* Bptr1 = B + (size_t)(b_row + 8) * N + n0 + b_col;

    float4 pa0 = *(const float4*)(Aptr);
    float4 pa1 = *(const float4*)(Aptr + 4);
    float4 pb0 = *(const float4*)(Bptr0);
    float4 pb1 = *(const float4*)(Bptr1);

    float acc[8][8];
    #pragma unroll
    for (int i = 0; i < 8; i++)
        #pragma unroll
        for (int j = 0; j < 8; j++) acc[i][j] = 0.f;

    int buf = 0;
    As[0][a_k+0][a_row]=pa0.x; As[0][a_k+1][a_row]=pa0.y;
    As[0][a_k+2][a_row]=pa0.z; As[0][a_k+3][a_row]=pa0.w;
    As[0][a_k+4][a_row]=pa1.x; As[0][a_k+5][a_row]=pa1.y;
    As[0][a_k+6][a_row]=pa1.z; As[0][a_k+7][a_row]=pa1.w;
    *(float4*)&Bs[0][b_row][b_col]   = pb0;
    *(float4*)&Bs[0][b_row+8][b_col] = pb1;
    __syncthreads();

    for (int k0 = 16; k0 < K; k0 += 16) {
        pa0 = *(const float4*)(Aptr + k0);
        pa1 = *(const float4*)(Aptr + k0 + 4);
        pb0 = *(const float4*)(Bptr0 + (size_t)k0 * N);
        pb1 = *(const float4*)(Bptr1 + (size_t)k0 * N);

        #pragma unroll
        for (int kk = 0; kk < 16; kk++) {
            float4 av0 = *(const float4*)&As[buf][kk][ty*8];
            float4 av1 = *(const float4*)&As[buf][kk][ty*8+4];
            float4 bv0 = *(const float4*)&Bs[buf][kk][tx*8];
            float4 bv1 = *(const float4*)&Bs[buf][kk][tx*8+4];
            float a[8] = {av0.x,av0.y,av0.z,av0.w,av1.x,av1.y,av1.z,av1.w};
            float b[8] = {bv0.x,bv0.y,bv0.z,bv0.w,bv1.x,bv1.y,bv1.z,bv1.w};
            #pragma unroll
            for (int i = 0; i < 8; i++)
                #pragma unroll
                for (int j = 0; j < 8; j++)
                    acc[i][j] = fmaf(a[i], b[j], acc[i][j]);
        }
        buf ^= 1;
        As[buf][a_k+0][a_row]=pa0.x; As[buf][a_k+1][a_row]=pa0.y;
        As[buf][a_k+2][a_row]=pa0.z; As[buf][a_k+3][a_row]=pa0.w;
        As[buf][a_k+4][a_row]=pa1.x; As[buf][a_k+5][a_row]=pa1.y;
        As[buf][a_k+6][a_row]=pa1.z; As[buf][a_k+7][a_row]=pa1.w;
        *(float4*)&Bs[buf][b_row][b_col]   = pb0;
        *(float4*)&Bs[buf][b_row+8][b_col] = pb1;
        __syncthreads();
    }
    #pragma unroll
    for (int kk = 0; kk < 16; kk++) {
        float4 av0 = *(const float4*)&As[buf][kk][ty*8];
        float4 av1 = *(const float4*)&As[buf][kk][ty*8+4];
        float4 bv0 = *(const float4*)&Bs[buf][kk][tx*8];
        float4 bv1 = *(const float4*)&Bs[buf][kk][tx*8+4];
        float a[8] = {av0.x,av0.y,av0.z,av0.w,av1.x,av1.y,av1.z,av1.w};
        float b[8] = {bv0.x,bv0.y,bv0.z,bv0.w,bv1.x,bv1.y,bv1.z,bv1.w};
        #pragma unroll
        for (int i = 0; i < 8; i++)
            #pragma unroll
            for (int j = 0; j < 8; j++)
                acc[i][j] = fmaf(a[i], b[j], acc[i][j]);
    }

    #pragma unroll
    for (int i = 0; i < 8; i++) {
        float* crow = C + (size_t)(m0 + ty * 8 + i) * N + n0 + tx * 8;
        float4 o0, o1;
        o0.x=acc[i][0]; o0.y=acc[i][1]; o0.z=acc[i][2]; o0.w=acc[i][3];
        o1.x=acc[i][4]; o1.y=acc[i][5]; o1.z=acc[i][6]; o1.w=acc[i][7];
        *(float4*)(crow)     = o0;
        *(float4*)(crow + 4) = o1;
    }
}

// ---------------- fused Q/K/V projection ----------------
// grid (18, 16): bx 0..15 -> Q columns, bx 16 -> K, bx 17 -> V
__global__ void __launch_bounds__(256)
fused_proj_kernel(const float* __restrict__ A,
                  const float* __restrict__ wq,
                  const float* __restrict__ wk,
                  const float* __restrict__ wv)
{
    const float* B; float* C; int N; int n0;
    const int bx = blockIdx.x;
    if (bx < 16)       { B = wq; C = g_q; N = DIMN;  n0 = bx * 128; }
    else if (bx == 16) { B = wk; C = g_k; N = DHEAD; n0 = 0; }
    else               { B = wv; C = g_v; N = DHEAD; n0 = 0; }
    gemm128_body(A, B, C, N, DIMN, blockIdx.y * 128, n0);
}

__global__ void __launch_bounds__(256)
out_gemm_kernel(const float* __restrict__ A,
                const float* __restrict__ B,
                float* __restrict__ C)
{
    gemm128_body(A, B, C, DIMN, DIMN, blockIdx.y * 128, blockIdx.x * 128);
}

// ---------------- suffix sums of V (two-phase, parallel) ----------------
__global__ void tilesum_kernel()
{
    const int t = blockIdx.x, d = threadIdx.x;
    float s = 0.f;
    for (int i = t * 64; i < (t + 1) * 64; i++)
        s += g_v[(size_t)i * DHEAD + d];
    g_tsum[t * DHEAD + d] = s;
}
__global__ void sufscan_kernel()
{
    const int d = threadIdx.x;
    float run = 0.f;
    g_sufv[NTILES * DHEAD + d] = 0.f;
    for (int t = NTILES - 1; t >= 0; t--) {
        run += g_tsum[t * DHEAD + d];
        g_sufv[t * DHEAD + d] = run;
    }
}

// ---------------- flash attention (register softmax, shuffle reductions) ------
// smem floats: Qs 64*129=8256, Ks 128*68=8704, Vs 64*132=8448, Ss 64*65=4160
#define FLASH_SMEM_FLOATS (8256 + 8704 + 8448 + 4160)

__global__ void __launch_bounds__(256)
flash_kernel(const float* __restrict__ bias)
{
    extern __shared__ float sm[];
    float* Qs = sm;
    float* Ks = sm + 8256;
    float* Vs = sm + 8256 + 8704;
    float* Ss = sm + 8256 + 8704 + 8448;

    const int tid = threadIdx.x;
    const int tx = tid & 15, ty = tid >> 4;
    const int i0 = blockIdx.x * 64;
    const int h  = blockIdx.y;

    for (int idx = tid; idx < 64 * 128; idx += 256) {
        int r = idx >> 7, d = idx & 127;
        Qs[r * 129 + d] = g_q[(size_t)(i0 + r) * DIMN + h * DHEAD + d] * SCALE_F;
    }

    float acc[4][8];
    #pragma unroll
    for (int i = 0; i < 4; i++)
        #pragma unroll
        for (int d = 0; d < 8; d++) acc[i][d] = 0.f;
    float m_run[4], l_run[4];
    #pragma unroll
    for (int i = 0; i < 4; i++) { m_run[i] = -INFINITY; l_run[i] = 0.f; }

    const int T = blockIdx.x + 1;
    for (int jt = 0; jt < T; jt++) {
        const int j0 = jt * 64;
        __syncthreads();   // prev PV done (and Qs visible on first iter)
        for (int idx = tid; idx < 64 * 128; idx += 256) {
            int jr = idx >> 7, d = idx & 127;
            Ks[d * 68 + jr]  = g_k[(size_t)(j0 + jr) * DHEAD + d];
            Vs[jr * 132 + d] = g_v[(size_t)(j0 + jr) * DHEAD + d];
        }
        __syncthreads();

        // scores 4x4
        float s[4][4];
        #pragma unroll
        for (int i = 0; i < 4; i++)
            #pragma unroll
            for (int j = 0; j < 4; j++) s[i][j] = 0.f;
        #pragma unroll 8
        for (int kk = 0; kk < 128; kk++) {
            float a[4], b[4];
            #pragma unroll
            for (int i = 0; i < 4; i++) a[i] = Qs[(ty * 4 + i) * 129 + kk];
            #pragma unroll
            for (int j = 0; j < 4; j++) b[j] = Ks[kk * 68 + tx * 4 + j];
            #pragma unroll
            for (int i = 0; i < 4; i++)
                #pragma unroll
                for (int j = 0; j < 4; j++)
                    s[i][j] = fmaf(a[i], b[j], s[i][j]);
        }
        // bias + mask
        #pragma unroll
        for (int i = 0; i < 4; i++) {
            const int gi = i0 + ty * 4 + i;
            const float* brow = bias + ((size_t)h * SEQN + gi) * SEQN + j0;
            #pragma unroll
            for (int j = 0; j < 4; j++) {
                const int jj = tx * 4 + j;
                float v = s[i][j] + brow[jj];
                s[i][j] = (j0 + jj > gi) ? 1e-10f : v;
            }
        }
        // online softmax in registers (16-lane shuffle reductions)
        float fac[4];
        #pragma unroll
        for (int i = 0; i < 4; i++) {
            float mt = fmaxf(fmaxf(s[i][0], s[i][1]), fmaxf(s[i][2], s[i][3]));
            #pragma unroll
            for (int off = 8; off; off >>= 1)
                mt = fmaxf(mt, __shfl_xor_sync(0xffffffffu, mt, off, 16));
            float mnew = fmaxf(m_run[i], mt);
            fac[i] = __expf(m_run[i] - mnew);
            m_run[i] = mnew;
            float sum = 0.f;
            #pragma unroll
            for (int j = 0; j < 4; j++) { s[i][j] = __expf(s[i][j] - mnew); sum += s[i][j]; }
            #pragma unroll
            for (int off = 8; off; off >>= 1)
                sum += __shfl_xor_sync(0xffffffffu, sum, off, 16);
            l_run[i] = l_run[i] * fac[i] + sum;
            #pragma unroll
            for (int j = 0; j < 4; j++) Ss[(ty * 4 + i) * 65 + tx * 4 + j] = s[i][j];
            #pragma unroll
            for (int d = 0; d < 8; d++) acc[i][d] *= fac[i];
        }
        __syncwarp();

        // P@V
        #pragma unroll 2
        for (int jj = 0; jj < 64; jj++) {
            float p[4];
            #pragma unroll
            for (int i = 0; i < 4; i++) p[i] = Ss[(ty * 4 + i) * 65 + jj];
            float4 v0 = *(float4*)&Vs[jj * 132 + tx * 8];
            float4 v1 = *(float4*)&Vs[jj * 132 + tx * 8 + 4];
            float vv[8] = {v0.x,v0.y,v0.z,v0.w,v1.x,v1.y,v1.z,v1.w};
            #pragma unroll
            for (int i = 0; i < 4; i++)
                #pragma unroll
                for (int d = 0; d < 8; d++)
                    acc[i][d] = fmaf(p[i], vv[d], acc[i][d]);
        }
    }

    // remaining fully-masked columns (value 1e-10), closed form via suffix sums
    const int rem = SEQN - T * 64;
    if (rem > 0) {
        #pragma unroll
        for (int i = 0; i < 4; i++) {
            float mnew = fmaxf(m_run[i], 1e-10f);
            float fac = __expf(m_run[i] - mnew);
            float e   = __expf(1e-10f - mnew);
            l_run[i] = l_run[i] * fac + (float)rem * e;
            #pragma unroll
            for (int d = 0; d < 8; d++)
                acc[i][d] = acc[i][d] * fac + e * g_sufv[T * DHEAD + tx * 8 + d];
        }
    }

    #pragma unroll
    for (int i = 0; i < 4; i++) {
        const float inv_l = 1.f / l_run[i];
        const int gi = i0 + ty * 4 + i;
        #pragma unroll
        for (int d = 0; d < 8; d++)
            g_ao[(size_t)gi * DIMN + h * DHEAD + tx * 8 + d] = acc[i][d] * inv_l;
    }
}

// ---------------- launch ----------------
extern "C" void kernel_launch(void* const* d_in, const int* in_sizes, int n_in,
                              void* d_out, int out_size)
{
    const float* x        = (const float*)d_in[0];
    const float* pos_bias = (const float*)d_in[1];
    const float* gamma    = (const float*)d_in[2];
    const float* wq       = (const float*)d_in[3];
    const float* wk       = (const float*)d_in[4];
    const float* wv       = (const float*)d_in[5];
    const float* wo       = (const float*)d_in[6];
    float* out = (float*)d_out;

    float *xn_p, *ao_p;
    cudaGetSymbolAddress((void**)&xn_p, g_xn);
    cudaGetSymbolAddress((void**)&ao_p, g_ao);

    cudaFuncSetAttribute(flash_kernel,
                         cudaFuncAttributeMaxDynamicSharedMemorySize,
                         FLASH_SMEM_FLOATS * (int)sizeof(float));

    rmsnorm_kernel<<<SEQN, 256>>>(x, gamma);
    fused_proj_kernel<<<dim3(18, 16), 256>>>(xn_p, wq, wk, wv);
    tilesum_kernel<<<NTILES, 128>>>();
    sufscan_kernel<<<1, 128>>>();
    flash_kernel<<<dim3(NTILES, HEADS), 256, FLASH_SMEM_FLOATS * sizeof(float)>>>(pos_bias);
    out_gemm_kernel<<<dim3(16, 16), 256>>>(ao_p, wo, out);
}

// round 14
// speedup vs baseline: 2.0682x; 1.3107x over previous
#include <cuda_runtime.h>
#include <cuda_bf16.h>
#include <math.h>
#include <stdint.h>

#define SEQN 2048
#define DIMN 2048
#define HEADS 16
#define DHEAD 128
#define NTILES 32
#define SCALE_F 0.08838834764831845f

// ---------------- device scratch ----------------
__device__ float g_q [SEQN * DIMN];
__device__ float g_k [SEQN * DHEAD];
__device__ float g_v [SEQN * DHEAD];
__device__ __nv_bfloat16 g_xn_h[SEQN * DIMN];
__device__ __nv_bfloat16 g_xn_l[SEQN * DIMN];
__device__ __nv_bfloat16 g_wqT_h[DIMN * DIMN];
__device__ __nv_bfloat16 g_wqT_l[DIMN * DIMN];
__device__ __nv_bfloat16 g_wkT_h[DHEAD * DIMN];
__device__ __nv_bfloat16 g_wkT_l[DHEAD * DIMN];
__device__ __nv_bfloat16 g_wvT_h[DHEAD * DIMN];
__device__ __nv_bfloat16 g_wvT_l[DHEAD * DIMN];
__device__ __nv_bfloat16 g_woT_h[DIMN * DIMN];
__device__ __nv_bfloat16 g_woT_l[DIMN * DIMN];
__device__ __nv_bfloat16 g_ao_h[SEQN * DIMN];
__device__ __nv_bfloat16 g_ao_l[SEQN * DIMN];
__device__ float g_tsum[NTILES * DHEAD];
__device__ float g_sufv[(NTILES + 1) * DHEAD];

// ---------------- PTX helpers (all sm_80+ baseline ISA) ----------------
__device__ __forceinline__ uint32_t smem_u32(const void* p) {
    uint32_t a;
    asm("{ .reg .u64 t; cvta.to.shared.u64 t, %1; cvt.u32.u64 %0, t; }" : "=r"(a) : "l"(p));
    return a;
}
__device__ __forceinline__ void cp16(uint32_t s, const void* g) {
    asm volatile("cp.async.cg.shared.global [%0], [%1], 16;" :: "r"(s), "l"(g));
}
#define CP_COMMIT() asm volatile("cp.async.commit_group;" ::: "memory")
#define CP_WAIT1()  asm volatile("cp.async.wait_group 1;" ::: "memory")
#define CP_WAIT0()  asm volatile("cp.async.wait_group 0;" ::: "memory")

__device__ __forceinline__ void ldm_x4(uint32_t& r0, uint32_t& r1, uint32_t& r2, uint32_t& r3, uint32_t a) {
    asm volatile("ldmatrix.sync.aligned.m8n8.x4.shared.b16 {%0,%1,%2,%3}, [%4];"
                 : "=r"(r0), "=r"(r1), "=r"(r2), "=r"(r3) : "r"(a));
}
__device__ __forceinline__ void ldm_x2(uint32_t& r0, uint32_t& r1, uint32_t a) {
    asm volatile("ldmatrix.sync.aligned.m8n8.x2.shared.b16 {%0,%1}, [%2];"
                 : "=r"(r0), "=r"(r1) : "r"(a));
}
__device__ __forceinline__ void mma16816(float* c, const uint32_t* a, const uint32_t* b) {
    asm volatile("mma.sync.aligned.m16n8k16.row.col.f32.bf16.bf16.f32 "
                 "{%0,%1,%2,%3}, {%4,%5,%6,%7}, {%8,%9}, {%0,%1,%2,%3};"
                 : "+f"(c[0]), "+f"(c[1]), "+f"(c[2]), "+f"(c[3])
                 : "r"(a[0]), "r"(a[1]), "r"(a[2]), "r"(a[3]), "r"(b[0]), "r"(b[1]));
}

// ---------------- RMSNorm -> bf16 hi/lo ----------------
__global__ void rmsnorm_kernel(const float* __restrict__ x,
                               const float* __restrict__ gamma)
{
    const int row = blockIdx.x;
    const int tid = threadIdx.x;
    const float4* xr4 = (const float4*)(x + (size_t)row * DIMN);
    const float4* g4  = (const float4*)gamma;

    float s = 0.f;
    float4 v0 = xr4[tid], v1 = xr4[tid + 256];
    s += v0.x*v0.x + v0.y*v0.y + v0.z*v0.z + v0.w*v0.w;
    s += v1.x*v1.x + v1.y*v1.y + v1.z*v1.z + v1.w*v1.w;
    #pragma unroll
    for (int o = 16; o; o >>= 1) s += __shfl_xor_sync(0xffffffffu, s, o);

    __shared__ float red[8];
    __shared__ float inv_sh;
    if ((tid & 31) == 0) red[tid >> 5] = s;
    __syncthreads();
    if (tid == 0) {
        float t = 0.f;
        #pragma unroll
        for (int i = 0; i < 8; i++) t += red[i];
        inv_sh = rsqrtf(t / (float)DIMN + 1e-5f);
    }
    __syncthreads();
    const float inv = inv_sh;
    float4 ga = g4[tid], gb = g4[tid + 256];
    float r0[4] = {v0.x*inv*ga.x, v0.y*inv*ga.y, v0.z*inv*ga.z, v0.w*inv*ga.w};
    float r1[4] = {v1.x*inv*gb.x, v1.y*inv*gb.y, v1.z*inv*gb.z, v1.w*inv*gb.w};

    __nv_bfloat16* oh = g_xn_h + (size_t)row * DIMN;
    __nv_bfloat16* ol = g_xn_l + (size_t)row * DIMN;
    #pragma unroll
    for (int i = 0; i < 4; i++) {
        __nv_bfloat16 h = __float2bfloat16(r0[i]);
        oh[tid * 4 + i] = h;
        ol[tid * 4 + i] = __float2bfloat16(r0[i] - __bfloat162float(h));
    }
    #pragma unroll
    for (int i = 0; i < 4; i++) {
        __nv_bfloat16 h = __float2bfloat16(r1[i]);
        oh[(tid + 256) * 4 + i] = h;
        ol[(tid + 256) * 4 + i] = __float2bfloat16(r1[i] - __bfloat162float(h));
    }
}

// ---------------- transpose + split: in[K][N] fp32 -> out[N][K] bf16 hi/lo ------
__global__ void transpose_split_kernel(const float* __restrict__ in,
                                       __nv_bfloat16* __restrict__ oh,
                                       __nv_bfloat16* __restrict__ ol,
                                       int K, int N)
{
    __shared__ float t[32][33];
    const int n0 = blockIdx.x * 32, k0 = blockIdx.y * 32;
    const int tx = threadIdx.x & 31, ty = threadIdx.x >> 5;  // 256 threads
    #pragma unroll
    for (int i = 0; i < 4; i++)
        t[ty + i * 8][tx] = in[(size_t)(k0 + ty + i * 8) * N + n0 + tx];
    __syncthreads();
    #pragma unroll
    for (int i = 0; i < 4; i++) {
        float v = t[tx][ty + i * 8];
        __nv_bfloat16 h = __float2bfloat16(v);
        size_t o = (size_t)(n0 + ty + i * 8) * K + k0 + tx;
        oh[o] = h;
        ol[o] = __float2bfloat16(v - __bfloat162float(h));
    }
}

// ---------------- warp-MMA bf16x3 GEMM: C[128,128] tile, K=2048 ----------------
// A[m][k] hi/lo, B[n][k] hi/lo (both K-major). C fp32.
// 256 threads = 8 warps in 2(m) x 4(n) grid; each warp 64x32 via m16n8k16 atoms.
// smem stage: Ah|Al|Bh|Bl tiles, each 128 rows x 32 bf16 @ pitch 40 bf16 (80B).
#define PITCH 40
#define TILE_B (128 * PITCH * 2)   // 10240
#define STAGE_B (4 * TILE_B)       // 40960
#define GEMM_SMEM (2 * STAGE_B)    // 81920
#define NKSTAGE (DIMN / 32)        // 64

__device__ __forceinline__ void wmma_gemm_body(
    const __nv_bfloat16* __restrict__ Ah, const __nv_bfloat16* __restrict__ Al,
    const __nv_bfloat16* __restrict__ Bh, const __nv_bfloat16* __restrict__ Bl,
    float* __restrict__ C, int ldc, int m0)
{
    extern __shared__ char smem[];
    const uint32_t sbase = smem_u32(smem);
    const int tid = threadIdx.x;
    const int warp = tid >> 5, lane = tid & 31;
    const int wm = (warp >> 2) * 64;       // 0 or 64
    const int wn = (warp & 3) * 32;        // 0,32,64,96
    const int l15 = lane & 15;

    // loader indices: each thread loads 2x16B per tile
    const int r = tid >> 1, half = tid & 1;
    const uint32_t soff = (uint32_t)(r * PITCH + half * 16) * 2;
    const size_t goffA = (size_t)(m0 + r) * DIMN + half * 16;
    const size_t goffB = (size_t)r * DIMN + half * 16;

    float acc[4][4][4];
    #pragma unroll
    for (int i = 0; i < 4; i++)
        #pragma unroll
        for (int j = 0; j < 4; j++)
            #pragma unroll
            for (int q = 0; q < 4; q++) acc[i][j][q] = 0.f;

    // ldmatrix base offsets (bytes) within a tile
    const uint32_t a_off = (uint32_t)(((wm + (lane & 15)) * PITCH + (lane >> 4) * 8) * 2);
    const uint32_t b_off = (uint32_t)(((wn + (l15 & 7)) * PITCH + ((l15 >> 3) & 1) * 8) * 2);

    // issue stage 0
    {
        uint32_t sb = sbase;
        cp16(sb + soff,              Ah + goffA); cp16(sb + soff + 16,              Ah + goffA + 8);
        cp16(sb + TILE_B + soff,     Al + goffA); cp16(sb + TILE_B + soff + 16,     Al + goffA + 8);
        cp16(sb + 2*TILE_B + soff,   Bh + goffB); cp16(sb + 2*TILE_B + soff + 16,   Bh + goffB + 8);
        cp16(sb + 3*TILE_B + soff,   Bl + goffB); cp16(sb + 3*TILE_B + soff + 16,   Bl + goffB + 8);
        CP_COMMIT();
    }

    for (int kt = 0; kt < NKSTAGE; kt++) {
        if (kt + 1 < NKSTAGE) {
            uint32_t sb = sbase + ((kt + 1) & 1) * STAGE_B;
            int k0 = (kt + 1) * 32;
            cp16(sb + soff,              Ah + goffA + k0); cp16(sb + soff + 16,              Ah + goffA + k0 + 8);
            cp16(sb + TILE_B + soff,     Al + goffA + k0); cp16(sb + TILE_B + soff + 16,     Al + goffA + k0 + 8);
            cp16(sb + 2*TILE_B + soff,   Bh + goffB + k0); cp16(sb + 2*TILE_B + soff + 16,   Bh + goffB + k0 + 8);
            cp16(sb + 3*TILE_B + soff,   Bl + goffB + k0); cp16(sb + 3*TILE_B + soff + 16,   Bl + goffB + k0 + 8);
            CP_COMMIT();
            CP_WAIT1();
        } else {
            CP_WAIT0();
        }
        __syncthreads();

        const uint32_t sb = sbase + (kt & 1) * STAGE_B;
        #pragma unroll
        for (int ks = 0; ks < 2; ks++) {
            const uint32_t kso = (uint32_t)(ks * 16 * 2);
            uint32_t ah[4][4], al[4][4], bh[4][2], bl[4][2];
            #pragma unroll
            for (int ma = 0; ma < 4; ma++) {
                uint32_t ao = a_off + (uint32_t)(ma * 16 * PITCH * 2) + kso;
                ldm_x4(ah[ma][0], ah[ma][1], ah[ma][2], ah[ma][3], sb + ao);
                ldm_x4(al[ma][0], al[ma][1], al[ma][2], al[ma][3], sb + TILE_B + ao);
            }
            #pragma unroll
            for (int nb = 0; nb < 4; nb++) {
                uint32_t bo = b_off + (uint32_t)(nb * 8 * PITCH * 2) + kso;
                ldm_x2(bh[nb][0], bh[nb][1], sb + 2*TILE_B + bo);
                ldm_x2(bl[nb][0], bl[nb][1], sb + 3*TILE_B + bo);
            }
            #pragma unroll
            for (int ma = 0; ma < 4; ma++)
                #pragma unroll
                for (int nb = 0; nb < 4; nb++) {
                    mma16816(acc[ma][nb], ah[ma], bh[nb]);
                    mma16816(acc[ma][nb], ah[ma], bl[nb]);
                    mma16816(acc[ma][nb], al[ma], bh[nb]);
                }
        }
        __syncthreads();
    }

    // epilogue: direct fp32 stores (float2 per atom-row-half)
    const int row_in = lane >> 2;
    const int col_in = (lane & 3) * 2;
    #pragma unroll
    for (int ma = 0; ma < 4; ma++) {
        #pragma unroll
        for (int nb = 0; nb < 4; nb++) {
            int mb = m0 + wm + ma * 16;
            int nc = wn + nb * 8 + col_in;
            float2 v0 = make_float2(acc[ma][nb][0], acc[ma][nb][1]);
            float2 v1 = make_float2(acc[ma][nb][2], acc[ma][nb][3]);
            *(float2*)&C[(size_t)(mb + row_in) * ldc + nc]     = v0;
            *(float2*)&C[(size_t)(mb + row_in + 8) * ldc + nc] = v1;
        }
    }
}

// grid (18, 16): bx 0..15 -> Q cols, 16 -> K, 17 -> V
__global__ void __launch_bounds__(256, 1)
proj_mma_kernel()
{
    const int bx = blockIdx.x;
    const int m0 = blockIdx.y * 128;
    const __nv_bfloat16 *Bh, *Bl; float* C; int ldc;
    if (bx < 16) {
        Bh = g_wqT_h + (size_t)bx * 128 * DIMN;
        Bl = g_wqT_l + (size_t)bx * 128 * DIMN;
        C = g_q + bx * 128; ldc = DIMN;
    } else if (bx == 16) {
        Bh = g_wkT_h; Bl = g_wkT_l; C = g_k; ldc = DHEAD;
    } else {
        Bh = g_wvT_h; Bl = g_wvT_l; C = g_v; ldc = DHEAD;
    }
    wmma_gemm_body(g_xn_h, g_xn_l, Bh, Bl, C, ldc, m0);
}

__global__ void __launch_bounds__(256, 1)
out_mma_kernel(float* __restrict__ out)
{
    const int bx = blockIdx.x;
    wmma_gemm_body(g_ao_h, g_ao_l,
                   g_woT_h + (size_t)bx * 128 * DIMN,
                   g_woT_l + (size_t)bx * 128 * DIMN,
                   out + bx * 128, DIMN, blockIdx.y * 128);
}

// ---------------- suffix sums of V ----------------
__global__ void tilesum_kernel()
{
    const int t = blockIdx.x, d = threadIdx.x;
    float s = 0.f;
    for (int i = t * 64; i < (t + 1) * 64; i++)
        s += g_v[(size_t)i * DHEAD + d];
    g_tsum[t * DHEAD + d] = s;
}
__global__ void sufscan_kernel()
{
    const int d = threadIdx.x;
    float vals[NTILES];
    #pragma unroll
    for (int t = 0; t < NTILES; t++) vals[t] = g_tsum[t * DHEAD + d];
    float run = 0.f;
    g_sufv[NTILES * DHEAD + d] = 0.f;
    #pragma unroll
    for (int t = NTILES - 1; t >= 0; t--) {
        run += vals[t];
        g_sufv[t * DHEAD + d] = run;
    }
}

// ---------------- flash attention (fp32, heavy tiles first) ----------------
#define FLASH_SMEM_FLOATS (8256 + 8704 + 8448 + 4160)

__global__ void __launch_bounds__(256)
flash_kernel(const float* __restrict__ bias)
{
    extern __shared__ float sm[];
    float* Qs = sm;
    float* Ks = sm + 8256;
    float* Vs = sm + 8256 + 8704;
    float* Ss = sm + 8256 + 8704 + 8448;

    const int tid = threadIdx.x;
    const int tx = tid & 15, ty = tid >> 4;
    const int xt = NTILES - 1 - blockIdx.x;   // heavy tiles scheduled first
    const int i0 = xt * 64;
    const int h  = blockIdx.y;

    for (int idx = tid; idx < 64 * 128; idx += 256) {
        int r = idx >> 7, d = idx & 127;
        Qs[r * 129 + d] = g_q[(size_t)(i0 + r) * DIMN + h * DHEAD + d] * SCALE_F;
    }

    float acc[4][8];
    #pragma unroll
    for (int i = 0; i < 4; i++)
        #pragma unroll
        for (int d = 0; d < 8; d++) acc[i][d] = 0.f;
    float m_run[4], l_run[4];
    #pragma unroll
    for (int i = 0; i < 4; i++) { m_run[i] = -INFINITY; l_run[i] = 0.f; }

    const int T = xt + 1;
    for (int jt = 0; jt < T; jt++) {
        const int j0 = jt * 64;
        __syncthreads();
        for (int idx = tid; idx < 64 * 128; idx += 256) {
            int jr = idx >> 7, d = idx & 127;
            Ks[d * 68 + jr]  = g_k[(size_t)(j0 + jr) * DHEAD + d];
            Vs[jr * 132 + d] = g_v[(size_t)(j0 + jr) * DHEAD + d];
        }
        __syncthreads();

        float s[4][4];
        #pragma unroll
        for (int i = 0; i < 4; i++)
            #pragma unroll
            for (int j = 0; j < 4; j++) s[i][j] = 0.f;
        #pragma unroll 8
        for (int kk = 0; kk < 128; kk++) {
            float a[4], b[4];
            #pragma unroll
            for (int i = 0; i < 4; i++) a[i] = Qs[(ty * 4 + i) * 129 + kk];
            #pragma unroll
            for (int j = 0; j < 4; j++) b[j] = Ks[kk * 68 + tx * 4 + j];
            #pragma unroll
            for (int i = 0; i < 4; i++)
                #pragma unroll
                for (int j = 0; j < 4; j++)
                    s[i][j] = fmaf(a[i], b[j], s[i][j]);
        }
        #pragma unroll
        for (int i = 0; i < 4; i++) {
            const int gi = i0 + ty * 4 + i;
            const float* brow = bias + ((size_t)h * SEQN + gi) * SEQN + j0;
            #pragma unroll
            for (int j = 0; j < 4; j++) {
                const int jj = tx * 4 + j;
                float v = s[i][j] + brow[jj];
                s[i][j] = (j0 + jj > gi) ? 1e-10f : v;
            }
        }
        float fac[4];
        #pragma unroll
        for (int i = 0; i < 4; i++) {
            float mt = fmaxf(fmaxf(s[i][0], s[i][1]), fmaxf(s[i][2], s[i][3]));
            #pragma unroll
            for (int off = 8; off; off >>= 1)
                mt = fmaxf(mt, __shfl_xor_sync(0xffffffffu, mt, off, 16));
            float mnew = fmaxf(m_run[i], mt);
            fac[i] = __expf(m_run[i] - mnew);
            m_run[i] = mnew;
            float sum = 0.f;
            #pragma unroll
            for (int j = 0; j < 4; j++) { s[i][j] = __expf(s[i][j] - mnew); sum += s[i][j]; }
            #pragma unroll
            for (int off = 8; off; off >>= 1)
                sum += __shfl_xor_sync(0xffffffffu, sum, off, 16);
            l_run[i] = l_run[i] * fac[i] + sum;
            #pragma unroll
            for (int j = 0; j < 4; j++) Ss[(ty * 4 + i) * 65 + tx * 4 + j] = s[i][j];
            #pragma unroll
            for (int d = 0; d < 8; d++) acc[i][d] *= fac[i];
        }
        __syncwarp();

        #pragma unroll 2
        for (int jj = 0; jj < 64; jj++) {
            float p[4];
            #pragma unroll
            for (int i = 0; i < 4; i++) p[i] = Ss[(ty * 4 + i) * 65 + jj];
            float4 v0 = *(float4*)&Vs[jj * 132 + tx * 8];
            float4 v1 = *(float4*)&Vs[jj * 132 + tx * 8 + 4];
            float vv[8] = {v0.x,v0.y,v0.z,v0.w,v1.x,v1.y,v1.z,v1.w};
            #pragma unroll
            for (int i = 0; i < 4; i++)
                #pragma unroll
                for (int d = 0; d < 8; d++)
                    acc[i][d] = fmaf(p[i], vv[d], acc[i][d]);
        }
    }

    const int rem = SEQN - T * 64;
    if (rem > 0) {
        #pragma unroll
        for (int i = 0; i < 4; i++) {
            float mnew = fmaxf(m_run[i], 1e-10f);
            float fac = __expf(m_run[i] - mnew);
            float e   = __expf(1e-10f - mnew);
            l_run[i] = l_run[i] * fac + (float)rem * e;
            #pragma unroll
            for (int d = 0; d < 8; d++)
                acc[i][d] = acc[i][d] * fac + e * g_sufv[T * DHEAD + tx * 8 + d];
        }
    }

    #pragma unroll
    for (int i = 0; i < 4; i++) {
        const float inv_l = 1.f / l_run[i];
        const int gi = i0 + ty * 4 + i;
        #pragma unroll
        for (int d = 0; d < 8; d++) {
            float val = acc[i][d] * inv_l;
            size_t o = (size_t)gi * DIMN + h * DHEAD + tx * 8 + d;
            __nv_bfloat16 hh = __float2bfloat16(val);
            g_ao_h[o] = hh;
            g_ao_l[o] = __float2bfloat16(val - __bfloat162float(hh));
        }
    }
}

// ---------------- launch ----------------
extern "C" void kernel_launch(void* const* d_in, const int* in_sizes, int n_in,
                              void* d_out, int out_size)
{
    const float* x        = (const float*)d_in[0];
    const float* pos_bias = (const float*)d_in[1];
    const float* gamma    = (const float*)d_in[2];
    const float* wq       = (const float*)d_in[3];
    const float* wk       = (const float*)d_in[4];
    const float* wv       = (const float*)d_in[5];
    const float* wo       = (const float*)d_in[6];
    float* out = (float*)d_out;

    __nv_bfloat16 *wqT_h, *wqT_l, *wkT_h, *wkT_l, *wvT_h, *wvT_l, *woT_h, *woT_l;
    cudaGetSymbolAddress((void**)&wqT_h, g_wqT_h);
    cudaGetSymbolAddress((void**)&wqT_l, g_wqT_l);
    cudaGetSymbolAddress((void**)&wkT_h, g_wkT_h);
    cudaGetSymbolAddress((void**)&wkT_l, g_wkT_l);
    cudaGetSymbolAddress((void**)&wvT_h, g_wvT_h);
    cudaGetSymbolAddress((void**)&wvT_l, g_wvT_l);
    cudaGetSymbolAddress((void**)&woT_h, g_woT_h);
    cudaGetSymbolAddress((void**)&woT_l, g_woT_l);

    cudaFuncSetAttribute(flash_kernel,
                         cudaFuncAttributeMaxDynamicSharedMemorySize,
                         FLASH_SMEM_FLOATS * (int)sizeof(float));
    cudaFuncSetAttribute(proj_mma_kernel,
                         cudaFuncAttributeMaxDynamicSharedMemorySize, GEMM_SMEM);
    cudaFuncSetAttribute(out_mma_kernel,
                         cudaFuncAttributeMaxDynamicSharedMemorySize, GEMM_SMEM);

    rmsnorm_kernel<<<SEQN, 256>>>(x, gamma);
    transpose_split_kernel<<<dim3(64, 64), 256>>>(wq, wqT_h, wqT_l, DIMN, DIMN);
    transpose_split_kernel<<<dim3(4, 64), 256>>>(wk, wkT_h, wkT_l, DIMN, DHEAD);
    transpose_split_kernel<<<dim3(4, 64), 256>>>(wv, wvT_h, wvT_l, DIMN, DHEAD);
    transpose_split_kernel<<<dim3(64, 64), 256>>>(wo, woT_h, woT_l, DIMN, DIMN);

    proj_mma_kernel<<<dim3(18, 16), 256, GEMM_SMEM>>>();

    tilesum_kernel<<<NTILES, 128>>>();
    sufscan_kernel<<<1, 128>>>();

    flash_kernel<<<dim3(NTILES, HEADS), 256, FLASH_SMEM_FLOATS * sizeof(float)>>>(pos_bias);

    out_mma_kernel<<<dim3(16, 16), 256, GEMM_SMEM>>>(out);
}